// round 3
// baseline (speedup 1.0000x reference)
#include <cuda_runtime.h>

// MultiHeadAttention: B=4, T=2048, C=1024, H=16, D=64
// Round 0 baseline: fp32 SGEMM (QKV) -> fp32 flash attention -> fp32 SGEMM (+bias)

#define B_ 4
#define T_ 2048
#define C_ 1024
#define H_ 16
#define D_ 64
#define M_ (B_ * T_)          // 8192
#define C3_ (3 * C_)          // 3072

// Scratch (allocation-free rule: __device__ globals)
__device__ float g_qkv[M_ * C3_];   // ~100.7 MB
__device__ float g_att[M_ * C_];    // ~33.6 MB

// ---------------------------------------------------------------------------
// Generic 128x128x16 SGEMM, row-major A[MxK] * B[KxN] -> C[MxN] (+ bias)
// All dims here are multiples of the tile sizes (8192, 3072/1024, 1024).
// ---------------------------------------------------------------------------
__global__ __launch_bounds__(256) void sgemm128(
    const float* __restrict__ A, const float* __restrict__ Bm,
    float* __restrict__ Cm, const float* __restrict__ bias,
    int M, int N, int K)
{
    constexpr int BM = 128, BN = 128, BK = 16, TM = 8, TN = 8;
    __shared__ float As[BK][BM];   // transposed A tile
    __shared__ float Bs[BK][BN];

    const int tid = threadIdx.x;
    const int tx = tid & 15;       // 16 thread cols
    const int ty = tid >> 4;       // 16 thread rows
    const int bx = blockIdx.x;
    const int by = blockIdx.y;

    const float* Ab = A + (size_t)by * BM * K;
    const float* Bb = Bm + (size_t)bx * BN;

    const int aRow = tid >> 2;            // 0..63
    const int aCol = (tid & 3) * 4;       // 0,4,8,12
    const int bRow = tid >> 5;            // 0..7
    const int bCol = (tid & 31) * 4;      // 0..124

    float acc[TM][TN] = {};

    for (int k0 = 0; k0 < K; k0 += BK) {
        #pragma unroll
        for (int i = 0; i < 2; i++) {
            int r = aRow + i * 64;
            float4 v = *(const float4*)(Ab + (size_t)r * K + k0 + aCol);
            As[aCol + 0][r] = v.x;
            As[aCol + 1][r] = v.y;
            As[aCol + 2][r] = v.z;
            As[aCol + 3][r] = v.w;
        }
        #pragma unroll
        for (int i = 0; i < 2; i++) {
            int r = bRow + i * 8;
            *(float4*)&Bs[r][bCol] = *(const float4*)(Bb + (size_t)(k0 + r) * N + bCol);
        }
        __syncthreads();

        #pragma unroll
        for (int kk = 0; kk < BK; kk++) {
            float ar[TM], br[TN];
            #pragma unroll
            for (int i = 0; i < TM; i += 4)
                *(float4*)&ar[i] = *(const float4*)&As[kk][ty * TM + i];
            #pragma unroll
            for (int j = 0; j < TN; j += 4)
                *(float4*)&br[j] = *(const float4*)&Bs[kk][tx * TN + j];
            #pragma unroll
            for (int i = 0; i < TM; i++)
                #pragma unroll
                for (int j = 0; j < TN; j++)
                    acc[i][j] += ar[i] * br[j];
        }
        __syncthreads();
    }

    #pragma unroll
    for (int i = 0; i < TM; i++) {
        int row = by * BM + ty * TM + i;
        #pragma unroll
        for (int j = 0; j < TN; j += 4) {
            int col = bx * BN + tx * TN + j;
            float4 v = make_float4(acc[i][j], acc[i][j + 1], acc[i][j + 2], acc[i][j + 3]);
            if (bias != nullptr) {
                v.x += bias[col + 0];
                v.y += bias[col + 1];
                v.z += bias[col + 2];
                v.w += bias[col + 3];
            }
            *(float4*)(Cm + (size_t)row * N + col) = v;
        }
    }
}

// ---------------------------------------------------------------------------
// Flash attention, fp32, causal. Grid: (T/128, H, B). 128 threads/CTA,
// thread t owns q-row q0+t fully in registers (q[64], o[64]).
// KV tiles of 64 rows staged in smem; scores in 16-wide chunks (online softmax).
// ---------------------------------------------------------------------------
__global__ __launch_bounds__(128) void flash_attn(
    const float* __restrict__ qkv, float* __restrict__ out)
{
    constexpr int BM = 128;   // q rows per CTA
    constexpr int BN = 64;    // kv rows per tile
    constexpr int CH = 16;    // score chunk

    __shared__ float Ks[BN][D_];
    __shared__ float Vs[BN][D_];

    const int tid = threadIdx.x;
    // reverse q-tile order: big-workload CTAs launch first (causal imbalance)
    const int qi = (int)gridDim.x - 1 - (int)blockIdx.x;
    const int h  = blockIdx.y;
    const int b  = blockIdx.z;
    const int q0 = qi * BM;
    const int qg = q0 + tid;

    const int base   = (b * T_) * C3_ + h * D_;  // token-0 offset for this (b,h)
    const int kbase  = base + C_;
    const int vbase  = base + 2 * C_;

    const float scale = 0.125f;   // 1/sqrt(64)

    float q[D_];
    {
        const float* qp = qkv + base + (size_t)qg * C3_;
        #pragma unroll
        for (int d = 0; d < D_; d += 4) {
            float4 v = *(const float4*)(qp + d);
            q[d + 0] = v.x * scale;
            q[d + 1] = v.y * scale;
            q[d + 2] = v.z * scale;
            q[d + 3] = v.w * scale;
        }
    }

    float o[D_];
    #pragma unroll
    for (int d = 0; d < D_; d++) o[d] = 0.f;
    float m = -1e30f;
    float l = 0.f;

    for (int j0 = 0; j0 <= q0 + BM - BN; j0 += BN) {
        // cooperative coalesced load of K and V tiles (64 x 64 each)
        #pragma unroll
        for (int it = 0; it < (BN * D_ / 4) / 128; it++) {   // 8 iters
            int idx = it * 128 + tid;
            int r = idx >> 4;             // D_/4 = 16 float4 per row
            int c = (idx & 15) * 4;
            int tok = (j0 + r) * C3_;
            *(float4*)&Ks[r][c] = *(const float4*)(qkv + kbase + tok + c);
            *(float4*)&Vs[r][c] = *(const float4*)(qkv + vbase + tok + c);
        }
        __syncthreads();

        const bool need_mask = (j0 + BN > q0);

        #pragma unroll 1
        for (int c0 = 0; c0 < BN; c0 += CH) {
            float s[CH];
            #pragma unroll
            for (int jj = 0; jj < CH; jj++) {
                const int j = c0 + jj;
                float acc = 0.f;
                #pragma unroll
                for (int d = 0; d < D_; d += 4) {
                    float4 kv = *(const float4*)&Ks[j][d];
                    acc += q[d + 0] * kv.x;
                    acc += q[d + 1] * kv.y;
                    acc += q[d + 2] * kv.z;
                    acc += q[d + 3] * kv.w;
                }
                if (need_mask && (j0 + j > qg)) acc = -1e30f;
                s[jj] = acc;
            }
            float cmax = s[0];
            #pragma unroll
            for (int jj = 1; jj < CH; jj++) cmax = fmaxf(cmax, s[jj]);
            const float nm = fmaxf(m, cmax);
            const float corr = __expf(m - nm);
            m = nm;
            l *= corr;
            #pragma unroll
            for (int d = 0; d < D_; d++) o[d] *= corr;
            #pragma unroll
            for (int jj = 0; jj < CH; jj++) {
                const float p = __expf(s[jj] - nm);
                l += p;
                const int j = c0 + jj;
                #pragma unroll
                for (int d = 0; d < D_; d += 4) {
                    float4 vv = *(const float4*)&Vs[j][d];
                    o[d + 0] += p * vv.x;
                    o[d + 1] += p * vv.y;
                    o[d + 2] += p * vv.z;
                    o[d + 3] += p * vv.w;
                }
            }
        }
        __syncthreads();
    }

    const float inv_l = 1.0f / l;
    float* op = out + ((size_t)(b * T_ + qg)) * C_ + h * D_;
    #pragma unroll
    for (int d = 0; d < D_; d += 4) {
        float4 v = make_float4(o[d] * inv_l, o[d + 1] * inv_l,
                               o[d + 2] * inv_l, o[d + 3] * inv_l);
        *(float4*)(op + d) = v;
    }
}

// ---------------------------------------------------------------------------
extern "C" void kernel_launch(void* const* d_in, const int* in_sizes, int n_in,
                              void* d_out, int out_size)
{
    const float* x     = (const float*)d_in[0];   // [B,T,C]
    const float* w_qkv = (const float*)d_in[1];   // [C,3C]
    const float* w_out = (const float*)d_in[2];   // [C,C]
    const float* b_out = (const float*)d_in[3];   // [C]
    float* out = (float*)d_out;                   // [B,T,C]

    float* qkv = nullptr;
    float* att = nullptr;
    cudaGetSymbolAddress((void**)&qkv, g_qkv);
    cudaGetSymbolAddress((void**)&att, g_att);

    // 1) QKV projection: [8192,1024] @ [1024,3072]
    sgemm128<<<dim3(C3_ / 128, M_ / 128), 256>>>(x, w_qkv, qkv, nullptr, M_, C3_, C_);

    // 2) Causal flash attention -> [B,T,C] (head-interleaved layout)
    flash_attn<<<dim3(T_ / 128, H_, B_), 128>>>(qkv, att);

    // 3) Output projection + bias: [8192,1024] @ [1024,1024]
    sgemm128<<<dim3(C_ / 128, M_ / 128), 256>>>(att, w_out, out, b_out, M_, C_, C_);
}

// round 5
// speedup vs baseline: 1.0138x; 1.0138x over previous
#include <cuda_runtime.h>
#include <cstdint>

// MultiHeadAttention: B=4, T=2048, C=1024, H=16, D=64
// R3: projection GEMMs on tensor pipe (mma.sync tf32, 3x-split for fp32 accuracy),
//     flash attention unchanged (scalar fp32, proven).

#define B_ 4
#define T_ 2048
#define C_ 1024
#define H_ 16
#define D_ 64
#define M_ (B_ * T_)          // 8192
#define C3_ (3 * C_)          // 3072

// Scratch (allocation-free rule: __device__ globals)
__device__ float g_qkv[M_ * C3_];   // ~100.7 MB
__device__ float g_att[M_ * C_];    // ~33.6 MB

// ---------------------------------------------------------------------------
// tf32 helpers
// ---------------------------------------------------------------------------
__device__ __forceinline__ void split_tf32(float x, uint32_t& h, uint32_t& l) {
    uint32_t hi;
    asm("cvt.rna.tf32.f32 %0, %1;" : "=r"(hi) : "f"(x));
    float r = x - __uint_as_float(hi);
    uint32_t lo;
    asm("cvt.rna.tf32.f32 %0, %1;" : "=r"(lo) : "f"(r));
    h = hi; l = lo;
}

__device__ __forceinline__ void mma_tf32(float c[4],
                                         uint32_t a0, uint32_t a1, uint32_t a2, uint32_t a3,
                                         uint32_t b0, uint32_t b1) {
    asm volatile(
        "mma.sync.aligned.m16n8k8.row.col.f32.tf32.tf32.f32 "
        "{%0,%1,%2,%3}, {%4,%5,%6,%7}, {%8,%9}, {%0,%1,%2,%3};\n"
        : "+f"(c[0]), "+f"(c[1]), "+f"(c[2]), "+f"(c[3])
        : "r"(a0), "r"(a1), "r"(a2), "r"(a3), "r"(b0), "r"(b1));
}

// ---------------------------------------------------------------------------
// 3xTF32 tensor-core GEMM: row-major A[MxK] * B[KxN] -> C[MxN] (+ bias)
// CTA: 128x128x16, 256 threads = 8 warps (2x4), warp tile 64x32 (4x4 mma grid).
// A smem [m][k] (stride 20), B smem [k][n] (stride 136): conflict-free frag LDS.
// ---------------------------------------------------------------------------
__global__ __launch_bounds__(256) void gemm_tf32x3(
    const float* __restrict__ A, const float* __restrict__ Bm,
    float* __restrict__ Cm, const float* __restrict__ bias,
    int M, int N, int K)
{
    constexpr int BM = 128, BN = 128, BK = 16;
    constexpr int AST = BK + 4;     // 20 floats per A row
    constexpr int BST = BN + 8;     // 136 floats per B row

    __shared__ float Ah[BM][AST], Al[BM][AST];
    __shared__ float Bh[BK][BST], Bl[BK][BST];

    const int tid  = threadIdx.x;
    const int wid  = tid >> 5;
    const int lane = tid & 31;
    const int wm   = wid >> 2;      // 0..1 -> 64-row band
    const int wn   = wid & 3;       // 0..3 -> 32-col band
    const int gr   = lane >> 2;     // 0..7
    const int tg   = lane & 3;      // 0..3

    const int bx = blockIdx.x, by = blockIdx.y;
    const float* Ab = A  + (size_t)by * BM * K;
    const float* Bb = Bm + (size_t)bx * BN;

    // gmem load mapping
    const int aRow = tid >> 2;          // 0..63 (and +64)
    const int aCol = (tid & 3) * 4;     // 0,4,8,12
    const int bRow = tid >> 5;          // 0..7 (and +8)
    const int bCol = (tid & 31) * 4;    // 0..124

    float acc[4][4][4];
    #pragma unroll
    for (int i = 0; i < 4; i++)
        #pragma unroll
        for (int j = 0; j < 4; j++)
            #pragma unroll
            for (int r = 0; r < 4; r++) acc[i][j][r] = 0.f;

    for (int k0 = 0; k0 < K; k0 += BK) {
        // --- A tile: 128x16, split hi/lo, store [m][k] ---
        #pragma unroll
        for (int i = 0; i < 2; i++) {
            int r = aRow + i * 64;
            float4 v = *(const float4*)(Ab + (size_t)r * K + k0 + aCol);
            float4 hv, lv;
            uint32_t h, l;
            split_tf32(v.x, h, l); hv.x = __uint_as_float(h); lv.x = __uint_as_float(l);
            split_tf32(v.y, h, l); hv.y = __uint_as_float(h); lv.y = __uint_as_float(l);
            split_tf32(v.z, h, l); hv.z = __uint_as_float(h); lv.z = __uint_as_float(l);
            split_tf32(v.w, h, l); hv.w = __uint_as_float(h); lv.w = __uint_as_float(l);
            *(float4*)&Ah[r][aCol] = hv;
            *(float4*)&Al[r][aCol] = lv;
        }
        // --- B tile: 16x128, split hi/lo, store [k][n] ---
        #pragma unroll
        for (int i = 0; i < 2; i++) {
            int r = bRow + i * 8;
            float4 v = *(const float4*)(Bb + (size_t)(k0 + r) * N + bCol);
            float4 hv, lv;
            uint32_t h, l;
            split_tf32(v.x, h, l); hv.x = __uint_as_float(h); lv.x = __uint_as_float(l);
            split_tf32(v.y, h, l); hv.y = __uint_as_float(h); lv.y = __uint_as_float(l);
            split_tf32(v.z, h, l); hv.z = __uint_as_float(h); lv.z = __uint_as_float(l);
            split_tf32(v.w, h, l); hv.w = __uint_as_float(h); lv.w = __uint_as_float(l);
            *(float4*)&Bh[r][bCol] = hv;
            *(float4*)&Bl[r][bCol] = lv;
        }
        __syncthreads();

        #pragma unroll
        for (int s = 0; s < 2; s++) {           // two k8 substeps per BK=16
            const int ks = s * 8;
            // A fragments for all 4 m-tiles (hi+lo): 32 regs
            uint32_t ah[4][4], al_[4][4];
            #pragma unroll
            for (int mi = 0; mi < 4; mi++) {
                const int m = wm * 64 + mi * 16 + gr;
                const int k = ks + tg;
                ah[mi][0]  = __float_as_uint(Ah[m    ][k    ]);
                ah[mi][1]  = __float_as_uint(Ah[m + 8][k    ]);
                ah[mi][2]  = __float_as_uint(Ah[m    ][k + 4]);
                ah[mi][3]  = __float_as_uint(Ah[m + 8][k + 4]);
                al_[mi][0] = __float_as_uint(Al[m    ][k    ]);
                al_[mi][1] = __float_as_uint(Al[m + 8][k    ]);
                al_[mi][2] = __float_as_uint(Al[m    ][k + 4]);
                al_[mi][3] = __float_as_uint(Al[m + 8][k + 4]);
            }
            #pragma unroll
            for (int ni = 0; ni < 4; ni++) {
                const int n  = wn * 32 + ni * 8 + gr;
                const int kb = ks + tg;
                uint32_t bh0 = __float_as_uint(Bh[kb    ][n]);
                uint32_t bh1 = __float_as_uint(Bh[kb + 4][n]);
                uint32_t bl0 = __float_as_uint(Bl[kb    ][n]);
                uint32_t bl1 = __float_as_uint(Bl[kb + 4][n]);
                #pragma unroll
                for (int mi = 0; mi < 4; mi++) {
                    mma_tf32(acc[mi][ni], ah[mi][0], ah[mi][1], ah[mi][2], ah[mi][3], bl0, bl1);
                    mma_tf32(acc[mi][ni], al_[mi][0], al_[mi][1], al_[mi][2], al_[mi][3], bh0, bh1);
                    mma_tf32(acc[mi][ni], ah[mi][0], ah[mi][1], ah[mi][2], ah[mi][3], bh0, bh1);
                }
            }
        }
        __syncthreads();
    }

    // --- epilogue: c frag (gr, 2*tg) / (+8), float2 stores ---
    #pragma unroll
    for (int mi = 0; mi < 4; mi++) {
        const int row0 = by * BM + wm * 64 + mi * 16 + gr;
        #pragma unroll
        for (int ni = 0; ni < 4; ni++) {
            const int col = bx * BN + wn * 32 + ni * 8 + tg * 2;
            float bx0 = 0.f, bx1 = 0.f;
            if (bias != nullptr) { bx0 = bias[col]; bx1 = bias[col + 1]; }
            float2 v0 = make_float2(acc[mi][ni][0] + bx0, acc[mi][ni][1] + bx1);
            float2 v1 = make_float2(acc[mi][ni][2] + bx0, acc[mi][ni][3] + bx1);
            *(float2*)(Cm + (size_t)row0 * N + col)       = v0;
            *(float2*)(Cm + (size_t)(row0 + 8) * N + col) = v1;
        }
    }
}

// ---------------------------------------------------------------------------
// Flash attention, fp32, causal. Grid: (T/128, H, B). 128 threads/CTA,
// thread t owns q-row q0+t fully in registers (q[64], o[64]).
// ---------------------------------------------------------------------------
__global__ __launch_bounds__(128) void flash_attn(
    const float* __restrict__ qkv, float* __restrict__ out)
{
    constexpr int BM = 128;   // q rows per CTA
    constexpr int BN = 64;    // kv rows per tile
    constexpr int CH = 16;    // score chunk

    __shared__ float Ks[BN][D_];
    __shared__ float Vs[BN][D_];

    const int tid = threadIdx.x;
    const int qi = (int)gridDim.x - 1 - (int)blockIdx.x;
    const int h  = blockIdx.y;
    const int b  = blockIdx.z;
    const int q0 = qi * BM;
    const int qg = q0 + tid;

    const int base   = (b * T_) * C3_ + h * D_;
    const int kbase  = base + C_;
    const int vbase  = base + 2 * C_;

    const float scale = 0.125f;

    float q[D_];
    {
        const float* qp = qkv + base + (size_t)qg * C3_;
        #pragma unroll
        for (int d = 0; d < D_; d += 4) {
            float4 v = *(const float4*)(qp + d);
            q[d + 0] = v.x * scale;
            q[d + 1] = v.y * scale;
            q[d + 2] = v.z * scale;
            q[d + 3] = v.w * scale;
        }
    }

    float o[D_];
    #pragma unroll
    for (int d = 0; d < D_; d++) o[d] = 0.f;
    float m = -1e30f;
    float l = 0.f;

    for (int j0 = 0; j0 <= q0 + BM - BN; j0 += BN) {
        #pragma unroll
        for (int it = 0; it < (BN * D_ / 4) / 128; it++) {
            int idx = it * 128 + tid;
            int r = idx >> 4;
            int c = (idx & 15) * 4;
            int tok = (j0 + r) * C3_;
            *(float4*)&Ks[r][c] = *(const float4*)(qkv + kbase + tok + c);
            *(float4*)&Vs[r][c] = *(const float4*)(qkv + vbase + tok + c);
        }
        __syncthreads();

        const bool need_mask = (j0 + BN > q0);

        #pragma unroll 1
        for (int c0 = 0; c0 < BN; c0 += CH) {
            float s[CH];
            #pragma unroll
            for (int jj = 0; jj < CH; jj++) {
                const int j = c0 + jj;
                float acc = 0.f;
                #pragma unroll
                for (int d = 0; d < D_; d += 4) {
                    float4 kv = *(const float4*)&Ks[j][d];
                    acc += q[d + 0] * kv.x;
                    acc += q[d + 1] * kv.y;
                    acc += q[d + 2] * kv.z;
                    acc += q[d + 3] * kv.w;
                }
                if (need_mask && (j0 + j > qg)) acc = -1e30f;
                s[jj] = acc;
            }
            float cmax = s[0];
            #pragma unroll
            for (int jj = 1; jj < CH; jj++) cmax = fmaxf(cmax, s[jj]);
            const float nm = fmaxf(m, cmax);
            const float corr = __expf(m - nm);
            m = nm;
            l *= corr;
            #pragma unroll
            for (int d = 0; d < D_; d++) o[d] *= corr;
            #pragma unroll
            for (int jj = 0; jj < CH; jj++) {
                const float p = __expf(s[jj] - nm);
                l += p;
                const int j = c0 + jj;
                #pragma unroll
                for (int d = 0; d < D_; d += 4) {
                    float4 vv = *(const float4*)&Vs[j][d];
                    o[d + 0] += p * vv.x;
                    o[d + 1] += p * vv.y;
                    o[d + 2] += p * vv.z;
                    o[d + 3] += p * vv.w;
                }
            }
        }
        __syncthreads();
    }

    const float inv_l = 1.0f / l;
    float* op = out + ((size_t)(b * T_ + qg)) * C_ + h * D_;
    #pragma unroll
    for (int d = 0; d < D_; d += 4) {
        float4 v = make_float4(o[d] * inv_l, o[d + 1] * inv_l,
                               o[d + 2] * inv_l, o[d + 3] * inv_l);
        *(float4*)(op + d) = v;
    }
}

// ---------------------------------------------------------------------------
extern "C" void kernel_launch(void* const* d_in, const int* in_sizes, int n_in,
                              void* d_out, int out_size)
{
    const float* x     = (const float*)d_in[0];   // [B,T,C]
    const float* w_qkv = (const float*)d_in[1];   // [C,3C]
    const float* w_out = (const float*)d_in[2];   // [C,C]
    const float* b_out = (const float*)d_in[3];   // [C]
    float* out = (float*)d_out;                   // [B,T,C]

    float* qkv = nullptr;
    float* att = nullptr;
    cudaGetSymbolAddress((void**)&qkv, g_qkv);
    cudaGetSymbolAddress((void**)&att, g_att);

    // 1) QKV projection: [8192,1024] @ [1024,3072]   (tensor pipe, 3xTF32)
    gemm_tf32x3<<<dim3(C3_ / 128, M_ / 128), 256>>>(x, w_qkv, qkv, nullptr, M_, C3_, C_);

    // 2) Causal flash attention -> [B,T,C]
    flash_attn<<<dim3(T_ / 128, H_, B_), 128>>>(qkv, att);

    // 3) Output projection + bias: [8192,1024] @ [1024,1024]   (tensor pipe, 3xTF32)
    gemm_tf32x3<<<dim3(C_ / 128, M_ / 128), 256>>>(att, w_out, out, b_out, M_, C_, C_);
}